// round 10
// baseline (speedup 1.0000x reference)
#include <cuda_runtime.h>
#include <math.h>
#include <stdint.h>

#define BB    1024     // batch rows
#define NN    8192     // samples per row
#define MM2   900      // half fold period (parity decimation)
#define NB    140      // bpm bins
#define NBP   144      // padded bins
#define NCH   9        // m-chunks
#define CHM   100      // m per chunk (9*100 = 900)
#define SLAB  10       // m per smem slab
#define CHF   1800     // fold-kernel chunk floats (2 fold periods)

// ---------------- device scratch ----------------
__device__ float2 d_fold[(size_t)BB * MM2];             // (ge, go)
__device__ float2 d_part[(size_t)BB * NCH * NBP];       // [row][chunk][bin] (s,c)
__device__ float  d_tl[BB];
__device__ float  d_fl[BB];

typedef unsigned long long ull;

// ---------------- f32x2 helpers ----------------
__device__ __forceinline__ ull pk2(float lo, float hi) {
    ull r;
    asm("mov.b64 %0, {%1, %2};" : "=l"(r) : "f"(lo), "f"(hi));
    return r;
}
__device__ __forceinline__ void fma2(ull& d, ull a, ull b) {
    asm("fma.rn.f32x2 %0, %1, %2, %0;" : "+l"(d) : "l"(a), "l"(b));
}

// ---------------- smem / mbarrier / bulk-copy helpers ----------------
__device__ __forceinline__ uint32_t smem_u32(const void* p) {
    uint32_t a;
    asm("{ .reg .u64 t; cvta.to.shared.u64 t, %1; cvt.u32.u64 %0, t; }"
        : "=r"(a) : "l"(p));
    return a;
}
__device__ __forceinline__ void mbar_init(uint32_t a, uint32_t cnt) {
    asm volatile("mbarrier.init.shared.b64 [%0], %1;" :: "r"(a), "r"(cnt) : "memory");
}
__device__ __forceinline__ void mbar_expect(uint32_t a, uint32_t bytes) {
    asm volatile("mbarrier.arrive.expect_tx.shared.b64 _, [%0], %1;"
                 :: "r"(a), "r"(bytes) : "memory");
}
__device__ __forceinline__ void bulk_g2s(uint32_t dst, const void* src,
                                         uint32_t bytes, uint32_t mbar) {
    asm volatile("cp.async.bulk.shared::cta.global.mbarrier::complete_tx::bytes "
                 "[%0], [%1], %2, [%3];"
                 :: "r"(dst), "l"(src), "r"(bytes), "r"(mbar) : "memory");
}
__device__ __forceinline__ void mbar_wait(uint32_t a, uint32_t parity) {
    uint32_t done;
    asm volatile(
        "{\n\t.reg .pred p;\n\t"
        "mbarrier.try_wait.parity.acquire.cta.shared::cta.b64 p, [%1], %2;\n\t"
        "selp.b32 %0, 1, 0, p;\n\t}"
        : "=r"(done) : "r"(a), "r"(parity) : "memory");
    if (!done) {
        asm volatile(
            "{\n\t.reg .pred P1;\n\t"
            "WL_%=:\n\t"
            "mbarrier.try_wait.parity.acquire.cta.shared::cta.b64 P1, [%0], %1, 0x989680;\n\t"
            "@P1 bra.uni WD_%=;\n\t"
            "bra.uni WL_%=;\n\t"
            "WD_%=:\n\t}"
            :: "r"(a), "r"(parity) : "memory");
    }
}

// ---------------- warp helpers ----------------
__device__ __forceinline__ float wsum(float v) {
    #pragma unroll
    for (int o = 16; o; o >>= 1) v += __shfl_down_sync(0xffffffffu, v, o);
    return v;
}
__device__ __forceinline__ float wallsum(float v) {
    #pragma unroll
    for (int o = 16; o; o >>= 1) v += __shfl_xor_sync(0xffffffffu, v, o);
    return v;
}
__device__ __forceinline__ float wallmax(float v) {
    #pragma unroll
    for (int o = 16; o; o >>= 1) v = fmaxf(v, __shfl_xor_sync(0xffffffffu, v, o));
    return v;
}

// ---------------- K1: TMA-pipelined pearson + parity fold --------------------
// 1024 threads; 5 chunks of 1800 floats (x and y) through 3 smem stages.
// thread t<900 privately owns fold-bin m=t (chunk = exactly 2 periods).
__global__ void __launch_bounds__(1024) k_fold(const float* __restrict__ x,
                                               const float* __restrict__ y) {
    __shared__ __align__(16) float sxs[3][CHF];   // 21.6 KB
    __shared__ __align__(16) float sys[3][CHF];   // 21.6 KB
    __shared__ ull mbar[3];
    __shared__ float red[32][5];

    int b = blockIdx.x, tid = threadIdx.x;
    int lane = tid & 31, warp = tid >> 5;

    uint32_t mb = smem_u32(mbar);
    uint32_t sxa = smem_u32(sxs), sya = smem_u32(sys);
    if (tid == 0) {
        mbar_init(mb, 1); mbar_init(mb + 8, 1); mbar_init(mb + 16, 1);
    }
    __syncthreads();

    const char* xg = (const char*)(x + (size_t)b * NN);
    const char* yg = (const char*)(y + (size_t)b * NN);

    if (tid == 0) {
        // chunk 0 -> stage 0, chunk 1 -> stage 1
        mbar_expect(mb, 2 * 7200u);
        bulk_g2s(sxa, xg, 7200u, mb);
        bulk_g2s(sya, yg, 7200u, mb);
        mbar_expect(mb + 8, 2 * 7200u);
        bulk_g2s(sxa + 7200, xg + 7200, 7200u, mb + 8);
        bulk_g2s(sya + 7200, yg + 7200, 7200u, mb + 8);
    }

    float sx = 0.f, sy = 0.f, sxy = 0.f, sxx = 0.f, syy = 0.f;
    float ge = 0.f, go = 0.f;
    const float W = 3.8349520e-4f;          // pi/8191

    #pragma unroll
    for (int c = 0; c < 5; c++) {
        int s = c % 3;
        if (tid == 0 && c + 2 < 5) {
            int cn = c + 2;
            int sn = cn % 3;
            uint32_t bytes = (cn < 4) ? 7200u : 3968u;
            mbar_expect(mb + 8 * sn, 2 * bytes);
            bulk_g2s(sxa + sn * 7200, xg + (size_t)cn * 7200, bytes, mb + 8 * sn);
            bulk_g2s(sya + sn * 7200, yg + (size_t)cn * 7200, bytes, mb + 8 * sn);
        }
        mbar_wait(mb + 8 * s, (c / 3) & 1);   // stage s: phase 0 at c=s, 1 at c=s+3

        if (tid < 900) {
            int nfl = (c < 4) ? CHF : 992;
            {   // j = 2c (even) -> +
                float xv = sxs[s][tid], yv = sys[s][tid];
                sx += xv; sy += yv; sxy += xv * yv; sxx += xv * xv; syy += yv * yv;
                float sn = __sinf((float)(c * CHF + tid) * W);
                float hx = xv * sn * sn;
                ge += hx; go += hx;
            }
            int i1 = tid + 900;
            if (i1 < nfl) {  // j = 2c+1 (odd) -> -
                float xv = sxs[s][i1], yv = sys[s][i1];
                sx += xv; sy += yv; sxy += xv * yv; sxx += xv * xv; syy += yv * yv;
                float sn = __sinf((float)(c * CHF + i1) * W);
                float hx = xv * sn * sn;
                ge += hx; go -= hx;
            }
        }
        __syncthreads();   // stage s free for reuse
    }

    if (tid < 900) d_fold[(size_t)b * MM2 + tid] = make_float2(ge, go);

    sx = wsum(sx); sy = wsum(sy); sxy = wsum(sxy); sxx = wsum(sxx); syy = wsum(syy);
    if (lane == 0) { red[warp][0]=sx; red[warp][1]=sy; red[warp][2]=sxy; red[warp][3]=sxx; red[warp][4]=syy; }
    __syncthreads();
    if (tid == 0) {
        double SX=0, SY=0, SXY=0, SXX=0, SYY=0;
        #pragma unroll
        for (int w = 0; w < 32; w++) {
            SX += red[w][0]; SY += red[w][1]; SXY += red[w][2];
            SXX += red[w][3]; SYY += red[w][4];
        }
        double num = (double)NN * SXY - SX * SY;
        double den = sqrt(((double)NN * SXX - SX * SX) * ((double)NN * SYY - SY * SY));
        d_tl[b] = (float)(1.0 - num / den);
    }
}

// ---------------- K2: 900-point parity NUDFT (R4 geometry, verbatim) --------
// grid (32 tiles, 9 chunks), block 288 = 36 tx * 8 ty; tile 4 rows x 4 bins
__global__ void __launch_bounds__(288, 2) k_dft() {
    __shared__ float sTab[SLAB * 2 * NBP];    // 10 m x 144 bins x (s,c)
    __shared__ float sGe[SLAB][32];
    __shared__ float sGo[SLAB][32];

    int tile  = blockIdx.x;
    int chunk = blockIdx.y;
    int tid = threadIdx.x;
    int tx = tid % 36;
    int ty = tid / 36;

    int rowBase = tile * 32;
    int mBase = chunk * CHM;

    int bk  = tid % NBP;
    int grp = tid / NBP;
    int freq = 40 + bk;

    ull acc[4][4] = {};
    const float* gp = (tx & 1) ? &sGo[0][0] : &sGe[0][0];
    const float ASCALE = 3.4906585e-3f;   // 2*pi/1800

    for (int step = 0; step < CHM / SLAB; step++) {
        int m0 = mBase + step * SLAB;
        __syncthreads();
        #pragma unroll
        for (int i = 0; i < 5; i++) {
            int mi = grp * 5 + i;
            float s = 0.f, c = 0.f;
            if (bk < NB) {
                int r = (freq * (m0 + mi)) % 1800;
                if (r >= 900) r -= 1800;
                __sincosf((float)r * ASCALE, &s, &c);
            }
            sTab[mi * (2 * NBP) + 2 * bk]     = s;
            sTab[mi * (2 * NBP) + 2 * bk + 1] = c;
        }
        if (tid < 160) {
            int r = tid & 31, q = tid >> 5;
            float4 v = *(const float4*)(d_fold + (size_t)(rowBase + r) * MM2 + m0 + 2 * q);
            sGe[2 * q][r]     = v.x;  sGo[2 * q][r]     = v.y;
            sGe[2 * q + 1][r] = v.z;  sGo[2 * q + 1][r] = v.w;
        }
        __syncthreads();

        #pragma unroll
        for (int mi = 0; mi < SLAB; mi++) {
            float4 g = *(const float4*)&gp[mi * 32 + 4 * ty];
            const ull* trow = (const ull*)&sTab[mi * (2 * NBP)];
            ull p0 = trow[tx];
            ull p1 = trow[tx + 36];
            ull p2 = trow[tx + 72];
            ull p3 = trow[tx + 108];
            float gr[4] = {g.x, g.y, g.z, g.w};
            #pragma unroll
            for (int r = 0; r < 4; r++) {
                ull g2 = pk2(gr[r], gr[r]);
                fma2(acc[r][0], g2, p0);
                fma2(acc[r][1], g2, p1);
                fma2(acc[r][2], g2, p2);
                fma2(acc[r][3], g2, p3);
            }
        }
    }

    #pragma unroll
    for (int r = 0; r < 4; r++) {
        int row = rowBase + 4 * ty + r;
        ull* dst = (ull*)(d_part + ((size_t)row * NCH + chunk) * NBP);
        dst[tx]       = acc[r][0];
        dst[tx + 36]  = acc[r][1];
        dst[tx + 72]  = acc[r][2];
        dst[tx + 108] = acc[r][3];
    }
}

// ---------------- K3: one block per row; thread = bin; no fences -------------
#define LT 160   // threads (5 warps); bins 0..143 active
__global__ void __launch_bounds__(LT) k_loss(const int* __restrict__ hr) {
    __shared__ float sh[8];
    __shared__ float shH;
    int tid = threadIdx.x;
    int lane = tid & 31, warp = tid >> 5;
    int row = blockIdx.x;
    bool valid = tid < NB;

    float s = 0.f, c = 0.f;
    if (valid) {
        const float2* pr = d_part + (size_t)row * NCH * NBP + tid;
        #pragma unroll
        for (int ch = 0; ch < NCH; ch++) {
            float2 v = pr[ch * NBP];
            s += v.x; c += v.y;
        }
    }
    float ca = valid ? (s * s + c * c) : 0.f;

    float v = wallsum(ca);
    if (lane == 0) sh[warp] = v;
    __syncthreads();
    float tot = sh[0] + sh[1] + sh[2] + sh[3] + sh[4];
    __syncthreads();

    float logit = ca / tot;

    v = wallmax(valid ? logit : -1e30f);
    if (lane == 0) sh[warp] = v;
    __syncthreads();
    float mx = fmaxf(fmaxf(fmaxf(sh[0], sh[1]), fmaxf(sh[2], sh[3])), sh[4]);
    __syncthreads();

    v = wallsum(valid ? expf(logit - mx) : 0.f);
    if (lane == 0) sh[warp] = v;
    __syncthreads();
    float lse = mx + logf(sh[0] + sh[1] + sh[2] + sh[3] + sh[4]);

    int h = hr[row];
    if (tid == h) shH = logit;
    __syncthreads();
    float ce = lse - shH;
    __syncthreads();

    float klc = 0.f;
    if (valid) {
        float dd = (float)tid - (float)h;
        float t = expf(-0.5f * dd * dd) * 0.3989422804014327f;
        t = fmaxf(t, 1e-15f);
        klc = expf(t) * (t - (logit - lse));
    }
    v = wallsum(klc);
    if (lane == 0) sh[warp] = v;
    __syncthreads();
    if (tid == 0) d_fl[row] = ce + (sh[0] + sh[1] + sh[2] + sh[3] + sh[4]) / (float)NB;
}

// ---------------- K4: final scalar ----------------
__global__ void __launch_bounds__(1024) k_final(const int* __restrict__ epoch_p,
                                                float* __restrict__ out) {
    __shared__ float r1[32], r2[32];
    int tid = threadIdx.x, lane = tid & 31, warp = tid >> 5;
    float a = d_tl[tid], c = d_fl[tid];
    a = wsum(a); c = wsum(c);
    if (lane == 0) { r1[warp] = a; r2[warp] = c; }
    __syncthreads();
    if (warp == 0) {
        a = wsum(r1[lane]);
        c = wsum(r2[lane]);
        if (lane == 0) {
            float tl = a / (float)BB;
            float fl = c / (float)BB;
            int epoch = epoch_p[0];
            float alpha, beta;
            if (epoch > 25) { alpha = 0.05f; beta = 2.0f; }
            else {
                float e = (float)epoch * 0.04f;       // epoch/25
                alpha = 0.1f * exp2f(-e);
                beta  = exp2f(e);
            }
            out[0] = alpha * tl + beta * fl;
        }
    }
}

// ---------------- launch ----------------
extern "C" void kernel_launch(void* const* d_in, const int* in_sizes, int n_in,
                              void* d_out, int out_size) {
    const int*   epoch_p = nullptr;
    const float* xp = nullptr;
    const float* yp = nullptr;
    const int*   hrp = nullptr;
    for (int i = 0; i < n_in; i++) {
        if (in_sizes[i] == 1 && !epoch_p) epoch_p = (const int*)d_in[i];
        else if (in_sizes[i] == BB * NN) { if (!xp) xp = (const float*)d_in[i]; else yp = (const float*)d_in[i]; }
        else if (in_sizes[i] == BB) hrp = (const int*)d_in[i];
    }
    float* out = (float*)d_out;

    k_fold<<<BB, 1024>>>(xp, yp);
    k_dft<<<dim3(32, NCH), 288>>>();
    k_loss<<<BB, LT>>>(hrp);
    k_final<<<1, 1024>>>(epoch_p, out);
    (void)out_size;
}

// round 11
// speedup vs baseline: 1.8253x; 1.8253x over previous
#include <cuda_runtime.h>
#include <math.h>
#include <stdint.h>

#define BB    1024     // batch rows
#define NN    8192     // samples per row
#define MM2   900      // half fold period (parity decimation)
#define NB    140      // bpm bins
#define NBP   144      // padded bins
#define NCH   9        // m-chunks
#define CHM   100      // m per chunk (9*100 = 900)
#define SLAB  10       // m per smem slab

// ---------------- device scratch ----------------
__device__ float2 d_fold[(size_t)BB * MM2];             // (ge, go)
__device__ float2 d_part[(size_t)BB * NCH * NBP];       // [row][chunk][bin] (s,c)
__device__ float  d_tl[BB];
__device__ float  d_fl[BB];

typedef unsigned long long ull;

// ---------------- f32x2 helpers ----------------
__device__ __forceinline__ ull pk2(float lo, float hi) {
    ull r;
    asm("mov.b64 %0, {%1, %2};" : "=l"(r) : "f"(lo), "f"(hi));
    return r;
}
__device__ __forceinline__ void fma2(ull& d, ull a, ull b) {
    asm("fma.rn.f32x2 %0, %1, %2, %0;" : "+l"(d) : "l"(a), "l"(b));
}

// ---------------- warp helpers ----------------
__device__ __forceinline__ float wsum(float v) {
    #pragma unroll
    for (int o = 16; o; o >>= 1) v += __shfl_down_sync(0xffffffffu, v, o);
    return v;
}
__device__ __forceinline__ float wallsum(float v) {
    #pragma unroll
    for (int o = 16; o; o >>= 1) v += __shfl_xor_sync(0xffffffffu, v, o);
    return v;
}
__device__ __forceinline__ float wallmax(float v) {
    #pragma unroll
    for (int o = 16; o; o >>= 1) v = fmaxf(v, __shfl_xor_sync(0xffffffffu, v, o));
    return v;
}

// ---------------- K1: pearson + parity fold, float4, SW-pipelined (depth 2) --
// thread t<225 owns m in {4t..4t+3}; float4 index q = t + 225*j is 16B-aligned
__global__ void __launch_bounds__(256) k_fold(const float* __restrict__ x,
                                              const float* __restrict__ y) {
    __shared__ float red[8][5];
    int b = blockIdx.x;
    int tid = threadIdx.x;
    int lane = tid & 31, warp = tid >> 5;

    const float4* xr = (const float4*)(x + (size_t)b * NN);
    const float4* yr = (const float4*)(y + (size_t)b * NN);
    const float W = 3.8349520e-4f;          // pi/8191
    const float4 Z = make_float4(0.f, 0.f, 0.f, 0.f);

    float sx = 0.f, sy = 0.f, sxy = 0.f, sxx = 0.f, syy = 0.f;
    float ge[4] = {}, go[4] = {};

    if (tid < 225) {
        float4 xv = xr[tid], yv = yr[tid];           // j = 0 (always in range)
        #pragma unroll
        for (int j = 0; j < 10; j++) {
            // prefetch j+1 (zero-filled when out of range)
            float4 xn = Z, yn = Z;
            if (j < 9) {
                int qn = tid + 225 * (j + 1);
                if (j + 1 < 9 || qn < 2048) { xn = xr[qn]; yn = yr[qn]; }
            }
            // process j
            sx += xv.x + xv.y + xv.z + xv.w;
            sy += yv.x + yv.y + yv.z + yv.w;
            sxy += xv.x*yv.x + xv.y*yv.y + xv.z*yv.z + xv.w*yv.w;
            sxx += xv.x*xv.x + xv.y*xv.y + xv.z*xv.z + xv.w*xv.w;
            syy += yv.x*yv.x + yv.y*yv.y + yv.z*yv.z + yv.w*yv.w;
            int n = 4 * (tid + 225 * j);
            float s0 = __sinf((float)(n)     * W);
            float s1 = __sinf((float)(n + 1) * W);
            float s2 = __sinf((float)(n + 2) * W);
            float s3 = __sinf((float)(n + 3) * W);
            float h0 = xv.x * s0 * s0, h1 = xv.y * s1 * s1;
            float h2 = xv.z * s2 * s2, h3 = xv.w * s3 * s3;
            ge[0] += h0; ge[1] += h1; ge[2] += h2; ge[3] += h3;
            if (j & 1) { go[0] -= h0; go[1] -= h1; go[2] -= h2; go[3] -= h3; }
            else       { go[0] += h0; go[1] += h1; go[2] += h2; go[3] += h3; }
            xv = xn; yv = yn;
        }
        float4* dst = (float4*)(d_fold + (size_t)b * MM2 + 4 * tid);
        dst[0] = make_float4(ge[0], go[0], ge[1], go[1]);
        dst[1] = make_float4(ge[2], go[2], ge[3], go[3]);
    }

    sx = wsum(sx); sy = wsum(sy); sxy = wsum(sxy); sxx = wsum(sxx); syy = wsum(syy);
    if (lane == 0) { red[warp][0]=sx; red[warp][1]=sy; red[warp][2]=sxy; red[warp][3]=sxx; red[warp][4]=syy; }
    __syncthreads();
    if (tid == 0) {
        double SX=0, SY=0, SXY=0, SXX=0, SYY=0;
        #pragma unroll
        for (int w = 0; w < 8; w++) {
            SX += red[w][0]; SY += red[w][1]; SXY += red[w][2];
            SXX += red[w][3]; SYY += red[w][4];
        }
        double num = (double)NN * SXY - SX * SY;
        double den = sqrt(((double)NN * SXX - SX * SX) * ((double)NN * SYY - SY * SY));
        d_tl[b] = (float)(1.0 - num / den);
    }
}

// ---------------- K2: 900-point parity NUDFT (R4 geometry, verbatim) --------
// grid (32 tiles, 9 chunks), block 288 = 36 tx * 8 ty; tile 4 rows x 4 bins
__global__ void __launch_bounds__(288, 2) k_dft() {
    __shared__ float sTab[SLAB * 2 * NBP];    // 10 m x 144 bins x (s,c)
    __shared__ float sGe[SLAB][32];
    __shared__ float sGo[SLAB][32];

    int tile  = blockIdx.x;
    int chunk = blockIdx.y;
    int tid = threadIdx.x;
    int tx = tid % 36;
    int ty = tid / 36;

    int rowBase = tile * 32;
    int mBase = chunk * CHM;

    int bk  = tid % NBP;
    int grp = tid / NBP;
    int freq = 40 + bk;

    ull acc[4][4] = {};
    const float* gp = (tx & 1) ? &sGo[0][0] : &sGe[0][0];
    const float ASCALE = 3.4906585e-3f;   // 2*pi/1800

    for (int step = 0; step < CHM / SLAB; step++) {
        int m0 = mBase + step * SLAB;
        __syncthreads();
        #pragma unroll
        for (int i = 0; i < 5; i++) {
            int mi = grp * 5 + i;
            float s = 0.f, c = 0.f;
            if (bk < NB) {
                int r = (freq * (m0 + mi)) % 1800;
                if (r >= 900) r -= 1800;
                __sincosf((float)r * ASCALE, &s, &c);
            }
            sTab[mi * (2 * NBP) + 2 * bk]     = s;
            sTab[mi * (2 * NBP) + 2 * bk + 1] = c;
        }
        if (tid < 160) {
            int r = tid & 31, q = tid >> 5;
            float4 v = *(const float4*)(d_fold + (size_t)(rowBase + r) * MM2 + m0 + 2 * q);
            sGe[2 * q][r]     = v.x;  sGo[2 * q][r]     = v.y;
            sGe[2 * q + 1][r] = v.z;  sGo[2 * q + 1][r] = v.w;
        }
        __syncthreads();

        #pragma unroll
        for (int mi = 0; mi < SLAB; mi++) {
            float4 g = *(const float4*)&gp[mi * 32 + 4 * ty];
            const ull* trow = (const ull*)&sTab[mi * (2 * NBP)];
            ull p0 = trow[tx];
            ull p1 = trow[tx + 36];
            ull p2 = trow[tx + 72];
            ull p3 = trow[tx + 108];
            float gr[4] = {g.x, g.y, g.z, g.w};
            #pragma unroll
            for (int r = 0; r < 4; r++) {
                ull g2 = pk2(gr[r], gr[r]);
                fma2(acc[r][0], g2, p0);
                fma2(acc[r][1], g2, p1);
                fma2(acc[r][2], g2, p2);
                fma2(acc[r][3], g2, p3);
            }
        }
    }

    #pragma unroll
    for (int r = 0; r < 4; r++) {
        int row = rowBase + 4 * ty + r;
        ull* dst = (ull*)(d_part + ((size_t)row * NCH + chunk) * NBP);
        dst[tx]       = acc[r][0];
        dst[tx + 36]  = acc[r][1];
        dst[tx + 72]  = acc[r][2];
        dst[tx + 108] = acc[r][3];
    }
}

// ---------------- K3: one block per row; thread = bin; no fences -------------
#define LT 160   // threads (5 warps); bins 0..143 active
__global__ void __launch_bounds__(LT) k_loss(const int* __restrict__ hr) {
    __shared__ float sh[8];
    __shared__ float shH;
    int tid = threadIdx.x;
    int lane = tid & 31, warp = tid >> 5;
    int row = blockIdx.x;
    bool valid = tid < NB;

    float s = 0.f, c = 0.f;
    if (valid) {
        const float2* pr = d_part + (size_t)row * NCH * NBP + tid;
        #pragma unroll
        for (int ch = 0; ch < NCH; ch++) {
            float2 v = pr[ch * NBP];
            s += v.x; c += v.y;
        }
    }
    float ca = valid ? (s * s + c * c) : 0.f;

    float v = wallsum(ca);
    if (lane == 0) sh[warp] = v;
    __syncthreads();
    float tot = sh[0] + sh[1] + sh[2] + sh[3] + sh[4];
    __syncthreads();

    float logit = ca / tot;

    v = wallmax(valid ? logit : -1e30f);
    if (lane == 0) sh[warp] = v;
    __syncthreads();
    float mx = fmaxf(fmaxf(fmaxf(sh[0], sh[1]), fmaxf(sh[2], sh[3])), sh[4]);
    __syncthreads();

    v = wallsum(valid ? expf(logit - mx) : 0.f);
    if (lane == 0) sh[warp] = v;
    __syncthreads();
    float lse = mx + logf(sh[0] + sh[1] + sh[2] + sh[3] + sh[4]);

    int h = hr[row];
    if (tid == h) shH = logit;
    __syncthreads();
    float ce = lse - shH;
    __syncthreads();

    float klc = 0.f;
    if (valid) {
        float dd = (float)tid - (float)h;
        float t = expf(-0.5f * dd * dd) * 0.3989422804014327f;
        t = fmaxf(t, 1e-15f);
        klc = expf(t) * (t - (logit - lse));
    }
    v = wallsum(klc);
    if (lane == 0) sh[warp] = v;
    __syncthreads();
    if (tid == 0) d_fl[row] = ce + (sh[0] + sh[1] + sh[2] + sh[3] + sh[4]) / (float)NB;
}

// ---------------- K4: final scalar (no FP64 pow) ----------------
__global__ void __launch_bounds__(1024) k_final(const int* __restrict__ epoch_p,
                                                float* __restrict__ out) {
    __shared__ float r1[32], r2[32];
    int tid = threadIdx.x, lane = tid & 31, warp = tid >> 5;
    float a = d_tl[tid], c = d_fl[tid];
    a = wsum(a); c = wsum(c);
    if (lane == 0) { r1[warp] = a; r2[warp] = c; }
    __syncthreads();
    if (warp == 0) {
        a = wsum(r1[lane]);
        c = wsum(r2[lane]);
        if (lane == 0) {
            float tl = a / (float)BB;
            float fl = c / (float)BB;
            int epoch = epoch_p[0];
            float alpha, beta;
            if (epoch > 25) { alpha = 0.05f; beta = 2.0f; }
            else {
                float e = (float)epoch * 0.04f;       // epoch/25
                alpha = 0.1f * exp2f(-e);
                beta  = exp2f(e);
            }
            out[0] = alpha * tl + beta * fl;
        }
    }
}

// ---------------- launch ----------------
extern "C" void kernel_launch(void* const* d_in, const int* in_sizes, int n_in,
                              void* d_out, int out_size) {
    const int*   epoch_p = nullptr;
    const float* xp = nullptr;
    const float* yp = nullptr;
    const int*   hrp = nullptr;
    for (int i = 0; i < n_in; i++) {
        if (in_sizes[i] == 1 && !epoch_p) epoch_p = (const int*)d_in[i];
        else if (in_sizes[i] == BB * NN) { if (!xp) xp = (const float*)d_in[i]; else yp = (const float*)d_in[i]; }
        else if (in_sizes[i] == BB) hrp = (const int*)d_in[i];
    }
    float* out = (float*)d_out;

    k_fold<<<BB, 256>>>(xp, yp);
    k_dft<<<dim3(32, NCH), 288>>>();
    k_loss<<<BB, LT>>>(hrp);
    k_final<<<1, 1024>>>(epoch_p, out);
    (void)out_size;
}